// round 17
// baseline (speedup 1.0000x reference)
#include <cuda_runtime.h>
#include <cuda_bf16.h>
#include <cuda_fp16.h>
#include <math.h>
#include <stdint.h>

#define NB 8
#define CCH 256
#define HW 4096
#define EPSF 1e-6f
#define NRC 128   /* CTAs per image in fused pass; each covers 32 rows */

// ---- scratch (device globals) ----
__device__ float g_ymu_part[NB * CCH];
__device__ float g_ymu[CCH];
__device__ __nv_bfloat16 g_xn[(size_t)NB * HW * CCH];
__device__ __nv_bfloat16 g_yn[(size_t)NB * HW * CCH];
__device__ __half g_D[(size_t)NB * HW * HW];
__device__ float g_part[(size_t)NB * NRC * HW];   // 16 MB partial col-max
__device__ float g_accum[NB];

__device__ __forceinline__ uint32_t smem_u32(const void* p) {
    uint32_t a;
    asm("{ .reg .u64 t; cvta.to.shared.u64 t, %1; cvt.u32.u64 %0, t; }" : "=r"(a) : "l"(p));
    return a;
}
__device__ __forceinline__ void mma_bf16(float* c, const uint32_t* a, const uint32_t* b) {
    asm volatile(
        "mma.sync.aligned.m16n8k16.row.col.f32.bf16.bf16.f32 "
        "{%0,%1,%2,%3}, {%4,%5,%6,%7}, {%8,%9}, {%0,%1,%2,%3};"
        : "+f"(c[0]), "+f"(c[1]), "+f"(c[2]), "+f"(c[3])
        : "r"(a[0]), "r"(a[1]), "r"(a[2]), "r"(a[3]), "r"(b[0]), "r"(b[1]));
}
__device__ __forceinline__ void ldsm_x4(uint32_t* r, uint32_t addr) {
    asm volatile("ldmatrix.sync.aligned.m8n8.x4.shared.b16 {%0,%1,%2,%3}, [%4];"
                 : "=r"(r[0]), "=r"(r[1]), "=r"(r[2]), "=r"(r[3]) : "r"(addr));
}
#define CP_ASYNC(dst, src) \
    asm volatile("cp.async.cg.shared.global [%0], [%1], 16;" :: "r"(dst), "l"(src))
#define CP_COMMIT() asm volatile("cp.async.commit_group;" ::: "memory")
#define CP_WAIT(n) asm volatile("cp.async.wait_group %0;" :: "n"(n) : "memory")

__device__ __forceinline__ uint32_t swz(int row, int ch) {
    return (uint32_t)(row * 64 + ((ch ^ ((row >> 1) & 3)) << 4));
}

// ---------------- K1a: per-(n,c) partial sum of y ----------------
__global__ void k_ymu_part(const float* __restrict__ y) {
    int c = blockIdx.x, n = blockIdx.y;
    const float* p = y + ((size_t)n * CCH + c) * HW;
    float s = 0.0f;
    #pragma unroll 4
    for (int t = threadIdx.x; t < HW; t += 256) s += p[t];
    #pragma unroll
    for (int o = 16; o > 0; o >>= 1)
        s += __shfl_xor_sync(0xffffffff, s, o);
    __shared__ float sh[8];
    if ((threadIdx.x & 31) == 0) sh[threadIdx.x >> 5] = s;
    __syncthreads();
    if (threadIdx.x == 0) {
        float t = 0.0f;
        #pragma unroll
        for (int w = 0; w < 8; w++) t += sh[w];
        g_ymu_part[n * CCH + c] = t;
    }
}
// K1b: reduce partials over n
__global__ void k_ymu_red() {
    int c = threadIdx.x;
    float s = 0.0f;
    #pragma unroll
    for (int n = 0; n < NB; n++) s += g_ymu_part[n * CCH + c];
    g_ymu[c] = s * (1.0f / (NB * HW));
}

// ---------------- K2: center + normalize over C, transpose, bf16 ----------------
__global__ void k_norm(const float* __restrict__ x, const float* __restrict__ y) {
    const float* src = blockIdx.z ? y : x;
    __nv_bfloat16* dst = blockIdx.z ? g_yn : g_xn;
    int n = blockIdx.y;
    int i0 = blockIdx.x * 32;

    __shared__ float sh[32 * 257];
    __shared__ float inv[32];

    const float* base = src + (size_t)n * CCH * HW + i0;
    int tid = threadIdx.x;
    int p = tid & 31, cl = tid >> 5;

    for (int cc = cl; cc < CCH; cc += 8)
        sh[p * 257 + cc] = base[(size_t)cc * HW + p] - g_ymu[cc];
    __syncthreads();
    if (tid < 32) {
        float ss = 0.0f;
        #pragma unroll 8
        for (int c = 0; c < CCH; c++) {
            float v = sh[tid * 257 + c];
            ss += v * v;
        }
        inv[tid] = rsqrtf(ss);
    }
    __syncthreads();
    __nv_bfloat16* out = dst + ((size_t)n * HW + i0) * CCH;
    for (int idx = tid; idx < 32 * CCH; idx += 256) {
        int pp = idx >> 8, c = idx & 255;
        out[idx] = __float2bfloat16(sh[pp * 257 + c] * inv[pp]);
    }
}

// ---------------- K3: HMMA bf16 GEMM, BK=32, 4-stage (64KB smem), staged epilogue ----------------
// grid (32, 32, NB), block 256 (8 warps: 4 in M x 2 in N), CTA tile 128x128
#define TROW 272
__global__ void __launch_bounds__(256, 2) k_gemm_mma() {
    extern __shared__ __align__(16) char smem[];

    int tid = threadIdx.x;
    int wid = tid >> 5, lane = tid & 31;
    int wm = wid >> 1, wn = wid & 1;

    int n = blockIdx.z;
    int i0 = blockIdx.x * 128, j0 = blockIdx.y * 128;

    const __nv_bfloat16* A = g_xn + ((size_t)n * HW + i0) * CCH;
    const __nv_bfloat16* B = g_yn + ((size_t)n * HW + j0) * CCH;

    uint32_t sbase = smem_u32(smem);
    const uint32_t B_OFF = 32768;

    int r0 = tid >> 2, c0 = tid & 3;
    int r1 = r0 + 64;
    uint32_t dA0 = swz(r0, c0), dA1 = swz(r1, c0);

    float acc[2][8][4];
    #pragma unroll
    for (int mf = 0; mf < 2; mf++)
        #pragma unroll
        for (int nf = 0; nf < 8; nf++)
            #pragma unroll
            for (int q = 0; q < 4; q++) acc[mf][nf][q] = 0.0f;

    int rowA[2], cAbase;
    {
        int m_in = lane & 15;
        cAbase = lane >> 4;
        rowA[0] = wm * 32 + m_in;
        rowA[1] = wm * 32 + 16 + m_in;
    }
    int rowB[4], cBbase;
    {
        int grp = lane >> 3;
        int n_off = (grp >> 1) * 8;
        cBbase = grp & 1;
        #pragma unroll
        for (int g = 0; g < 4; g++)
            rowB[g] = wn * 64 + g * 16 + n_off + (lane & 7);
    }

    #pragma unroll
    for (int s = 0; s < 3; s++) {
        int k0 = s * 32;
        uint32_t so = (uint32_t)s * 8192;
        CP_ASYNC(sbase + so + dA0, A + (size_t)r0 * CCH + k0 + c0 * 8);
        CP_ASYNC(sbase + so + dA1, A + (size_t)r1 * CCH + k0 + c0 * 8);
        CP_ASYNC(sbase + B_OFF + so + dA0, B + (size_t)r0 * CCH + k0 + c0 * 8);
        CP_ASYNC(sbase + B_OFF + so + dA1, B + (size_t)r1 * CCH + k0 + c0 * 8);
        CP_COMMIT();
    }

    #pragma unroll 1
    for (int s = 0; s < 8; s++) {
        CP_WAIT(2);
        __syncthreads();

        if (s + 3 < 8) {
            int k0 = (s + 3) * 32;
            uint32_t so = (uint32_t)((s + 3) & 3) * 8192;
            CP_ASYNC(sbase + so + dA0, A + (size_t)r0 * CCH + k0 + c0 * 8);
            CP_ASYNC(sbase + so + dA1, A + (size_t)r1 * CCH + k0 + c0 * 8);
            CP_ASYNC(sbase + B_OFF + so + dA0, B + (size_t)r0 * CCH + k0 + c0 * 8);
            CP_ASYNC(sbase + B_OFF + so + dA1, B + (size_t)r1 * CCH + k0 + c0 * 8);
        }
        CP_COMMIT();

        uint32_t sA = sbase + (uint32_t)(s & 3) * 8192;
        uint32_t sB = sbase + B_OFF + (uint32_t)(s & 3) * 8192;

        #pragma unroll
        for (int t = 0; t < 2; t++) {
            int kc = t * 2;
            uint32_t a[2][4];
            #pragma unroll
            for (int mf = 0; mf < 2; mf++) {
                int row = rowA[mf];
                uint32_t addr = sA + (uint32_t)(row * 64 + (((cAbase + kc) ^ ((row >> 1) & 3)) << 4));
                ldsm_x4(a[mf], addr);
            }
            uint32_t breg[16];
            #pragma unroll
            for (int g = 0; g < 4; g++) {
                int row = rowB[g];
                uint32_t addr = sB + (uint32_t)(row * 64 + (((cBbase + kc) ^ ((row >> 1) & 3)) << 4));
                ldsm_x4(breg + g * 4, addr);
            }
            #pragma unroll
            for (int mf = 0; mf < 2; mf++)
                #pragma unroll
                for (int nf = 0; nf < 8; nf++)
                    mma_bf16(acc[mf][nf], a[mf], breg + ((nf >> 1) * 4 + (nf & 1) * 2));
        }
    }

    CP_WAIT(0);
    __syncthreads();

    {
        int rrel0 = wm * 32 + (lane >> 2);
        int crel = wn * 64 + (lane & 3) * 2;
        #pragma unroll
        for (int mf = 0; mf < 2; mf++) {
            #pragma unroll
            for (int nf = 0; nf < 8; nf++) {
                int r = rrel0 + mf * 16;
                int c = crel + nf * 8;
                __half2 h0 = __floats2half2_rn(1.0f - acc[mf][nf][0], 1.0f - acc[mf][nf][1]);
                __half2 h1 = __floats2half2_rn(1.0f - acc[mf][nf][2], 1.0f - acc[mf][nf][3]);
                *reinterpret_cast<__half2*>(smem + r * TROW + c * 2) = h0;
                *reinterpret_cast<__half2*>(smem + (r + 8) * TROW + c * 2) = h1;
            }
        }
    }
    __syncthreads();

    {
        __half* Dn = g_D + (size_t)n * HW * HW;
        #pragma unroll
        for (int k = 0; k < 8; k++) {
            int idx = tid + 256 * k;
            int row = idx >> 4, ch = idx & 15;
            uint4 v = *reinterpret_cast<const uint4*>(smem + row * TROW + ch * 16);
            *reinterpret_cast<uint4*>(Dn + (size_t)(i0 + row) * HW + j0 + ch * 8) = v;
        }
    }
}

// ---------------- K4: fused pass — one D read: per-row (a,b) + CTA col-max partial ----------------
// grid (NRC, NB), block 256 (8 warps). Warp w owns cols [w*512, (w+1)*512) of ALL rows.
// CTA covers 32 rows = 4 octets of 8. Col-max over 32 rows is register-resident per lane.
__global__ void __launch_bounds__(256) k_fused() {
    __shared__ float sm_min[8][8];   // [row][warp]
    __shared__ float sm_sum[8][8];
    int tid = threadIdx.x;
    int w = tid >> 5, l = tid & 31;
    int n = blockIdx.y;
    int ibase = blockIdx.x * 32;

    float cmax[16];
    #pragma unroll
    for (int k = 0; k < 16; k++) cmax[k] = -3.4e38f;

    #pragma unroll 1
    for (int oct = 0; oct < 4; oct++) {
        int i0 = ibase + oct * 8;
        const uint4* base = reinterpret_cast<const uint4*>(g_D + ((size_t)n * HW + i0) * HW);

        // load 8 rows x 2 chunks (lane covers cols w*512 + l*8..+8 and +256)
        uint4 v[8][2];
        #pragma unroll
        for (int r = 0; r < 8; r++) {
            v[r][0] = base[(size_t)r * 512 + w * 64 + l];
            v[r][1] = base[(size_t)r * 512 + w * 64 + 32 + l];
        }

        // per-row warp-partial min
        #pragma unroll
        for (int r = 0; r < 8; r++) {
            const __half2* h0 = reinterpret_cast<const __half2*>(&v[r][0]);
            const __half2* h1 = reinterpret_cast<const __half2*>(&v[r][1]);
            __half2 m2 = __hmin2(__hmin2(h0[0], h0[1]), __hmin2(h0[2], h0[3]));
            m2 = __hmin2(m2, __hmin2(__hmin2(h1[0], h1[1]), __hmin2(h1[2], h1[3])));
            float mn = fminf(__low2float(m2), __high2float(m2));
            #pragma unroll
            for (int o = 16; o > 0; o >>= 1)
                mn = fminf(mn, __shfl_xor_sync(0xffffffff, mn, o));
            if (l == 0) sm_min[r][w] = mn;
        }
        __syncthreads();

        // every thread derives a_r from warp partials
        float aR[8];
        #pragma unroll
        for (int r = 0; r < 8; r++) {
            float mn = sm_min[r][0];
            #pragma unroll
            for (int q = 1; q < 8; q++) mn = fminf(mn, sm_min[r][q]);
            aR[r] = 2.0f / (mn + EPSF);
        }

        // per-row warp-partial exp sum
        #pragma unroll
        for (int r = 0; r < 8; r++) {
            float s = 0.0f;
            #pragma unroll
            for (int c = 0; c < 2; c++) {
                const __half2* h = reinterpret_cast<const __half2*>(&v[r][c]);
                #pragma unroll
                for (int q = 0; q < 4; q++) {
                    float2 f = __half22float2(h[q]);
                    s += __expf(fmaf(-aR[r], f.x, 2.0f)) + __expf(fmaf(-aR[r], f.y, 2.0f));
                }
            }
            #pragma unroll
            for (int o = 16; o > 0; o >>= 1)
                s += __shfl_xor_sync(0xffffffff, s, o);
            if (l == 0) sm_sum[r][w] = s;
        }
        __syncthreads();

        float bR[8];
        #pragma unroll
        for (int r = 0; r < 8; r++) {
            float t = sm_sum[r][0];
            #pragma unroll
            for (int q = 1; q < 8; q++) t += sm_sum[r][q];
            bR[r] = 2.0f - __logf(t);
        }

        // register-resident col-max over these 8 rows (no syncs)
        #pragma unroll
        for (int r = 0; r < 8; r++) {
            #pragma unroll
            for (int c = 0; c < 2; c++) {
                const __half2* h = reinterpret_cast<const __half2*>(&v[r][c]);
                #pragma unroll
                for (int q = 0; q < 4; q++) {
                    float2 f = __half22float2(h[q]);
                    cmax[c * 8 + 2 * q]     = fmaxf(cmax[c * 8 + 2 * q],     fmaf(-aR[r], f.x, bR[r]));
                    cmax[c * 8 + 2 * q + 1] = fmaxf(cmax[c * 8 + 2 * q + 1], fmaf(-aR[r], f.y, bR[r]));
                }
            }
        }
    }

    // flush this CTA's 4096-col partial (coalesced float4 stores)
    float* out = g_part + ((size_t)n * NRC + blockIdx.x) * HW + w * 512 + l * 8;
    #pragma unroll
    for (int c = 0; c < 2; c++) {
        float4 lo = make_float4(cmax[c * 8 + 0], cmax[c * 8 + 1], cmax[c * 8 + 2], cmax[c * 8 + 3]);
        float4 hi = make_float4(cmax[c * 8 + 4], cmax[c * 8 + 5], cmax[c * 8 + 6], cmax[c * 8 + 7]);
        *reinterpret_cast<float4*>(out + c * 256)     = lo;
        *reinterpret_cast<float4*>(out + c * 256 + 4) = hi;
    }
}

// ---------------- K5: reduce partials over NRC, exp, sum ----------------
// grid (NB), block 1024
__global__ void k_colreduce() {
    int n = blockIdx.x, tid = threadIdx.x;
    float s = 0.0f;
    #pragma unroll
    for (int k = 0; k < 4; k++) {
        int j = tid + k * 1024;
        float m = -3.4e38f;
        #pragma unroll 8
        for (int p = 0; p < NRC; p++)
            m = fmaxf(m, g_part[((size_t)n * NRC + p) * HW + j]);
        s += __expf(m);
    }
    __shared__ float sh[1024];
    sh[tid] = s;
    __syncthreads();
    for (int o = 512; o > 0; o >>= 1) {
        if (tid < o) sh[tid] += sh[tid + o];
        __syncthreads();
    }
    if (tid == 0) g_accum[n] = sh[0];
}

// ---------------- K6: final loss ----------------
__global__ void k_final(float* __restrict__ out) {
    if (threadIdx.x == 0) {
        float s = 0.0f;
        for (int n = 0; n < NB; n++)
            s += -logf(g_accum[n] * (1.0f / HW) + EPSF);
        out[0] = s * (1.0f / NB);
    }
}

extern "C" void kernel_launch(void* const* d_in, const int* in_sizes, int n_in,
                              void* d_out, int out_size) {
    const float* x = (const float*)d_in[0];
    const float* y = (const float*)d_in[1];
    float* out = (float*)d_out;

    cudaFuncSetAttribute(k_gemm_mma, cudaFuncAttributeMaxDynamicSharedMemorySize, 65536);

    k_ymu_part<<<dim3(CCH, NB), 256>>>(y);
    k_ymu_red<<<1, 256>>>();
    k_norm<<<dim3(HW / 32, NB, 2), 256>>>(x, y);
    k_gemm_mma<<<dim3(HW / 128, HW / 128, NB), 256, 65536>>>();
    k_fused<<<dim3(NRC, NB), 256>>>();
    k_colreduce<<<NB, 1024>>>();
    k_final<<<1, 32>>>(out);
}